// round 14
// baseline (speedup 1.0000x reference)
#include <cuda_runtime.h>
#include <math.h>

// ---------------- problem constants ----------------
#define NBATCH 2
#define NCH    2
#define NSRC   4
#define NFFT   4096
#define HOP    1024
#define NBINS  2049
#define NFRM   600
#define WINLEN 300
#define NCHUNK 2
#define TLEN   613376
#define PAD    2048
#define EPSV   1e-10f
#define SQEPS  1e-5f
#define OUTLEN (NFFT + HOP*(NFRM-1))   // 617472
#define NHOP   601
#define FOWN   15
#define NSTRIP 40                       // 40*15 = 600; hop 600 handled by last strip

// exchange row strides (bank-conflict-free for float2/LDS.64, 512 cols)
#define ST1 514
#define ST2 520
#define SBUF (8*ST2)

// ---------------- device scratch ----------------
__device__ float2 d_rt[NBINS];
__device__ float  d_win[NFFT];
__device__ float  d_wsuminv[OUTLEN];
__device__ unsigned int d_maxsq[NBATCH*NCHUNK];
__device__ float4 d_X4[(size_t)NBATCH*NFRM*NBINS];             // (x0.re,x0.im,x1.re,x1.im)
__device__ float4 d_W[(size_t)NBATCH*NFRM*NBINS];              // ma*p*(w0,w1)
__device__ float  d_G[(size_t)NBATCH*NCHUNK*NBINS*4];          // raw G accumulators
__device__ float4 d_Gs[(size_t)NBATCH*NCHUNK*NBINS];           // scaled G
__device__ float  d_A[(size_t)NBATCH*NCHUNK*NBINS];            // sum of coefs
__device__ float  d_coef[(size_t)NBATCH*NCHUNK*NSRC*NBINS];    // per-source bin coef
// boundary handoff buffers: [ns][strip][3 hops][1024 samples], (ch0,ch1)
__device__ float2 d_head[(size_t)NBATCH*NSRC*NSTRIP*3*HOP];
__device__ float2 d_tail[(size_t)NBATCH*NSRC*NSTRIP*3*HOP];

__device__ __forceinline__ float2 cmul(float2 a, float2 b) {
    return make_float2(a.x*b.x - a.y*b.y, a.x*b.y + a.y*b.x);
}
__device__ __forceinline__ float2 cadd(float2 a, float2 b) { return make_float2(a.x+b.x, a.y+b.y); }
__device__ __forceinline__ float2 csub(float2 a, float2 b) { return make_float2(a.x-b.x, a.y-b.y); }

template<bool INV>
__device__ __forceinline__ float2 mul_pm_i(float2 d) {
    return INV ? make_float2(-d.y, d.x) : make_float2(d.y, -d.x);
}

// ---------------- init ----------------
__global__ void init_kernel() {
    int i = blockIdx.x * blockDim.x + threadIdx.x;
    if (i < NBINS) {
        double ang = -2.0 * M_PI * (double)i / (double)NFFT;
        d_rt[i] = make_float2((float)cos(ang), (float)sin(ang));
    }
    if (i < NFFT) {
        double w = 0.5 * (1.0 - cos(2.0 * M_PI * (double)i / (double)NFFT));
        d_win[i]  = (float)w;
    }
    if (i < NBATCH*NCHUNK) d_maxsq[i] = 0u;
}

// ---------------- init2: wsuminv (all-float) + zero G ----------------
__global__ void init2_kernel() {
    int i = blockIdx.x * blockDim.x + threadIdx.x;
    if (i < NBATCH*NCHUNK*NBINS*4) d_G[i] = 0.f;
    if (i >= OUTLEN) return;
    int fhi = min(NFRM - 1, i >> 10);
    int flo = max(0, (i - (NFFT - HOP)) >> 10);
    float wsum = 0.f;
    for (int f = flo; f <= fhi; f++) {
        float w = d_win[i - (f << 10)];
        wsum += w * w;
    }
    d_wsuminv[i] = 1.f / (wsum > 1e-11f ? wsum : 1.f);
}

// ---------------- radix-8 DFT in registers ----------------
template<bool INV>
__device__ __forceinline__ void dft8(const float2 a[8], float2 r[8]) {
    const float s = 0.70710678118654752440f;
    float2 t0 = cadd(a[0], a[4]);
    float2 t1 = csub(a[0], a[4]);
    float2 t2 = cadd(a[2], a[6]);
    float2 t3 = mul_pm_i<INV>(csub(a[2], a[6]));
    float2 E0 = cadd(t0, t2), E1 = cadd(t1, t3), E2 = csub(t0, t2), E3 = csub(t1, t3);
    float2 u0 = cadd(a[1], a[5]);
    float2 u1 = csub(a[1], a[5]);
    float2 u2 = cadd(a[3], a[7]);
    float2 u3 = mul_pm_i<INV>(csub(a[3], a[7]));
    float2 O0 = cadd(u0, u2), O1 = cadd(u1, u3), O2 = csub(u0, u2), O3 = csub(u1, u3);
    float2 O1t, O2t, O3t;
    if (!INV) {
        O1t = make_float2(s*(O1.x + O1.y), s*(O1.y - O1.x));
        O2t = make_float2(O2.y, -O2.x);
        O3t = make_float2(s*(O3.y - O3.x), -s*(O3.x + O3.y));
    } else {
        O1t = make_float2(s*(O1.x - O1.y), s*(O1.x + O1.y));
        O2t = make_float2(-O2.y, O2.x);
        O3t = make_float2(-s*(O3.x + O3.y), s*(O3.x - O3.y));
    }
    r[0] = cadd(E0, O0);  r[4] = csub(E0, O0);
    r[1] = cadd(E1, O1t); r[5] = csub(E1, O1t);
    r[2] = cadd(E2, O2t); r[6] = csub(E2, O2t);
    r[3] = cadd(E3, O3t); r[7] = csub(E3, O3t);
}

// serial twiddle chain (lower register pressure than product tree)
template<bool INV>
__device__ __forceinline__ void twiddle8(float2 r[8], int jm) {
    float2 w1 = d_rt[jm];
    if (INV) w1.y = -w1.y;
    float2 w = w1;
    #pragma unroll
    for (int q = 1; q < 8; q++) {
        r[q] = cmul(r[q], w);
        if (q < 7) w = cmul(w, w1);
    }
}

// ---------------- 4096-pt radix-8 Stockham: regs + 3 float2 smem exchanges, 512 thr ----------------
template<bool INV>
__device__ void fft4096_reg(float2 a[8], float2* __restrict__ sC, int tid) {
    float2 r[8];
    dft8<INV>(a, r);
    twiddle8<INV>(r, tid);
    #pragma unroll
    for (int q = 0; q < 8; q++) sC[q*ST1 + tid] = r[q];
    __syncthreads();
    #pragma unroll
    for (int q = 0; q < 8; q++) {
        int p = tid + q*512;
        a[q] = sC[(p & 7)*ST1 + (p >> 3)];
    }
    __syncthreads();
    dft8<INV>(a, r);
    twiddle8<INV>(r, tid - (tid & 7));
    #pragma unroll
    for (int q = 0; q < 8; q++) sC[q*ST2 + tid] = r[q];
    __syncthreads();
    #pragma unroll
    for (int q = 0; q < 8; q++) {
        int p = tid + q*512;
        int row = (p >> 3) & 7, col = ((p >> 6) << 3) | (p & 7);
        a[q] = sC[row*ST2 + col];
    }
    __syncthreads();
    dft8<INV>(a, r);
    twiddle8<INV>(r, tid - (tid & 63));
    #pragma unroll
    for (int q = 0; q < 8; q++) sC[q*ST2 + tid] = r[q];
    __syncthreads();
    #pragma unroll
    for (int q = 0; q < 8; q++) {
        int p = tid + q*512;
        int row = (p >> 6) & 7, col = ((p >> 9) << 6) | (p & 63);
        a[q] = sC[row*ST2 + col];
    }
    __syncthreads();
    dft8<INV>(a, r);
    #pragma unroll
    for (int q = 0; q < 8; q++) a[q] = r[q];
}

// ---------------- STFT: one block per (n,frame); both channels packed ----------------
__global__ __launch_bounds__(512) void stft_kernel(const float* __restrict__ audio) {
    __shared__ float2 sC[SBUF];
    __shared__ float red[512];
    int bid = blockIdx.x;                 // n*600 + f
    int f   = bid % NFRM;
    int n   = bid / NFRM;
    int tid = threadIdx.x;
    const float* a0 = audio + (size_t)(n*NCH + 0) * TLEN;
    const float* a1 = audio + (size_t)(n*NCH + 1) * TLEN;
    int base = f * HOP - PAD;

    float2 a[8];
    #pragma unroll
    for (int q = 0; q < 8; q++) {
        int t = tid + q*512;
        int j = base + t;
        if (j < 0) j = -j; else if (j >= TLEN) j = 2*TLEN - 2 - j;
        float w = d_win[t];
        a[q] = make_float2(a0[j] * w, a1[j] * w);
    }
    fft4096_reg<false>(a, sC, tid);

    #pragma unroll
    for (int q = 0; q < 8; q++) sC[tid + q*512] = a[q];
    __syncthreads();

    float4* out = d_X4 + ((size_t)n * NFRM + f) * NBINS;
    float lmax = 0.f;
    for (int k = tid; k < NBINS; k += 512) {
        int kb = (NFFT - k) & (NFFT - 1);
        float2 Zk = sC[k];
        float2 Zm = sC[kb];
        float x0r = 0.5f*(Zk.x + Zm.x), x0i = 0.5f*(Zk.y - Zm.y);
        float x1r = 0.5f*(Zk.y + Zm.y), x1i = 0.5f*(Zm.x - Zk.x);
        out[k] = make_float4(x0r, x0i, x1r, x1i);
        lmax = fmaxf(lmax, fmaxf(x0r*x0r + x0i*x0i, x1r*x1r + x1i*x1i));
    }
    red[tid] = lmax; __syncthreads();
    for (int s2 = 256; s2 > 0; s2 >>= 1) {
        if (tid < s2) red[tid] = fmaxf(red[tid], red[tid + s2]);
        __syncthreads();
    }
    if (tid == 0)
        atomicMax(&d_maxsq[n * NCHUNK + f / WINLEN], __float_as_uint(red[0]));
}

// ---------------- wiener pass A: raw spatial covariance G (t-split, atomic) ----------------
__global__ __launch_bounds__(256) void wiener_g_kernel() {
    __shared__ float sred[4][8][32];
    int nchunk = blockIdx.y;
    int seg = blockIdx.z;
    int n = nchunk >> 1, chunk = nchunk & 1;
    int tid = threadIdx.x;
    int bi = tid & 31, tg = tid >> 5;
    int b = blockIdx.x * 32 + bi;
    bool valid = (b < NBINS);
    int bc = valid ? b : 0;

    const float4* xp = d_X4 + ((size_t)n * NFRM + chunk*WINLEN + seg*15) * NBINS + bc;

    float g00 = 0.f, g11 = 0.f, g01r = 0.f, g01i = 0.f;
    for (int t = tg; t < 15; t += 8) {
        float4 v = xp[(size_t)t * NBINS];
        g00 += v.x*v.x + v.y*v.y;
        g11 += v.z*v.z + v.w*v.w;
        g01r += v.x*v.z + v.y*v.w;
        g01i += v.y*v.z - v.x*v.w;
    }
    sred[0][tg][bi] = g00; sred[1][tg][bi] = g11;
    sred[2][tg][bi] = g01r; sred[3][tg][bi] = g01i;
    __syncthreads();
    if (tg == 0 && valid) {
        g00 = g11 = g01r = g01i = 0.f;
        #pragma unroll
        for (int k = 0; k < 8; k++) {
            g00 += sred[0][k][bi]; g11 += sred[1][k][bi];
            g01r += sred[2][k][bi]; g01i += sred[3][k][bi];
        }
        float* gp = d_G + ((size_t)nchunk * NBINS + b) * 4;
        atomicAdd(gp + 0, g00);
        atomicAdd(gp + 1, g11);
        atomicAdd(gp + 2, g01r);
        atomicAdd(gp + 3, g01i);
    }
}

// ---------------- wiener pass B: per-bin coefs ----------------
__global__ void wiener_coef_kernel(const float* __restrict__ W) {
    int id = blockIdx.x * blockDim.x + threadIdx.x;
    if (id >= NBATCH*NCHUNK*NBINS) return;
    int b = id % NBINS;
    int nchunk = id / NBINS;
    float maxsq = __uint_as_float(d_maxsq[nchunk]);
    float ma = fmaxf(1.f, sqrtf(maxsq) * 0.1f);
    float inv_ma2 = 1.f / (ma * ma);
    const float* gp = d_G + (size_t)id * 4;
    float g00 = gp[0] * inv_ma2;
    float g11 = gp[1] * inv_ma2;
    float g01r = gp[2] * inv_ma2;
    float g01i = gp[3] * inv_ma2;
    float P = 0.5f * (g00 + g11);
    float A = 0.f;
    #pragma unroll
    for (int s = 0; s < NSRC; s++) {
        float m  = 1.f / (1.f + expf(-W[s * NBINS + b]));
        float m2 = m * m;
        float c = (m2 * m2) / (EPSV + m2 * P);
        A += c;
        d_coef[((size_t)(nchunk * NSRC + s)) * NBINS + b] = c;
    }
    d_Gs[id] = make_float4(g00, g11, g01r, g01i);
    d_A[id] = A;
}

// ---------------- wiener pass C: apply per (n,t,b) ----------------
__global__ __launch_bounds__(256) void wiener_apply_kernel() {
    size_t id = (size_t)blockIdx.x * blockDim.x + threadIdx.x;
    const size_t total = (size_t)NBATCH * NFRM * NBINS;
    if (id >= total) return;
    int b = (int)(id % NBINS);
    int nf = (int)(id / NBINS);
    int f = nf % NFRM;
    int n = nf / NFRM;
    int nchunk = n * NCHUNK + (f >= WINLEN ? 1 : 0);

    float maxsq = __uint_as_float(d_maxsq[nchunk]);
    float ma = fmaxf(1.f, sqrtf(maxsq) * 0.1f);
    float inv_ma = 1.f / ma;

    float4 v = d_X4[id];
    float4 g4 = d_Gs[(size_t)nchunk * NBINS + b];
    float A = d_A[(size_t)nchunk * NBINS + b];
    float g00 = g4.x, g11 = g4.y, g01r = g4.z, g01i = g4.w;

    float2 x0 = make_float2(v.x*inv_ma, v.y*inv_ma);
    float2 x1 = make_float2(v.z*inv_ma, v.w*inv_ma);
    float p = 0.5f * (x0.x*x0.x + x0.y*x0.y + x1.x*x1.x + x1.y*x1.y);
    float bt = p * A;
    float c00 = SQEPS + bt * g00;
    float c11 = SQEPS + bt * g11;
    float c01r = bt * g01r, c01i = bt * g01i;
    float det = c00 * c11 - (c01r*c01r + c01i*c01i);
    float idet = 1.f / det;
    float2 u0, u1;
    u0.x = idet * (c11 * x0.x - (c01r * x1.x - c01i * x1.y));
    u0.y = idet * (c11 * x0.y - (c01r * x1.y + c01i * x1.x));
    u1.x = idet * ((-c01r * x0.x - c01i * x0.y) + c00 * x1.x);
    u1.y = idet * (( c01i * x0.x - c01r * x0.y) + c00 * x1.y);
    float2 w0, w1;
    w0.x = g00 * u0.x + g01r * u1.x - g01i * u1.y;
    w0.y = g00 * u0.y + g01r * u1.y + g01i * u1.x;
    w1.x = g01r * u0.x + g01i * u0.y + g11 * u1.x;
    w1.y = g01r * u0.y - g01i * u0.x + g11 * u1.y;
    float sc = ma * p;
    d_W[id] = make_float4(sc*w0.x, sc*w0.y, sc*w1.x, sc*w1.y);
}

// ---------------- fused iSTFT + OLA, no halo (boundary handoff), 3 blocks/SM ----------------
__global__ __launch_bounds__(512, 3) void istft_ola_kernel(float* __restrict__ out) {
    __shared__ float2 sC[SBUF];
    __shared__ float2 sAcc[NFFT];
    int bid = blockIdx.x;          // ns*NSTRIP + strip
    int strip = bid % NSTRIP;
    int ns = bid / NSTRIP;         // n*4 + s
    int n = ns >> 2;
    int s = ns & 3;
    int tid = threadIdx.x;

    int h0 = strip * FOWN;
    int fend = min(NFRM, h0 + FOWN);

    float* o0 = out + ((size_t)ns * NCH + 0) * TLEN;
    float* o1 = out + ((size_t)ns * NCH + 1) * TLEN;
    float2* headp = d_head + ((size_t)(ns * NSTRIP + strip) * 3) * HOP;
    float2* tailp = d_tail + ((size_t)(ns * NSTRIP + strip) * 3) * HOP;

    #pragma unroll
    for (int q = 0; q < 8; q++) sAcc[tid + q*512] = make_float2(0.f, 0.f);
    __syncthreads();

    const float inv_n = 1.f / (float)NFFT;

    for (int f = h0; f < fend; f++) {
        int chunk = f / WINLEN;
        const float4* Wrow = d_W + ((size_t)n * NFRM + f) * NBINS;
        const float*  crow = d_coef + ((size_t)((n*NCHUNK + chunk) * NSRC + s)) * NBINS;

        float2 a[8];
        #pragma unroll
        for (int q = 0; q < 8; q++) {
            int j = tid + q*512;
            int k = (j <= 2048) ? j : (NFFT - j);
            float4 w4 = Wrow[k];
            float cc  = crow[k];
            if (j <= 2048)
                a[q] = make_float2(cc * (w4.x - w4.w), cc * (w4.y + w4.z));
            else
                a[q] = make_float2(cc * (w4.x + w4.w), cc * (w4.z - w4.y));
        }
        fft4096_reg<true>(a, sC, tid);

        int fb = (f << 10);
        bool head = (f - h0 < 3) && (h0 > 0);   // partial hop (prev strip contributes)
        // finalize hop f: ring + in-register a[0],a[1]; zero slots
        #pragma unroll
        for (int u = 0; u < 2; u++) {
            int p = tid + u*512;
            int jj = fb + p;
            int slot = jj & (NFFT - 1);
            float w = inv_n * d_win[p];
            float2 v = sAcc[slot];
            v.x += a[u].x * w;
            v.y += a[u].y * w;
            sAcc[slot] = make_float2(0.f, 0.f);
            if (head) {
                headp[(f - h0) * HOP + p] = v;
            } else {
                int t = jj - PAD;
                if (t >= 0 && t < TLEN) {
                    float wi = d_wsuminv[jj];
                    o0[t] = v.x * wi;
                    o1[t] = v.y * wi;
                }
            }
        }
        // tail accumulate (hops f+1..f+3): disjoint slots from finalize
        #pragma unroll
        for (int q = 2; q < 8; q++) {
            int p = tid + q*512;
            int slot = (fb + p) & (NFFT - 1);
            float w = inv_n * d_win[p];
            float2 acc = sAcc[slot];
            sAcc[slot] = make_float2(acc.x + a[q].x * w, acc.y + a[q].y * w);
        }
        __syncthreads();
    }

    if (fend < NFRM) {
        // hand off ring tail (partials for hops fend..fend+2) to next strip
        #pragma unroll
        for (int j = 0; j < 3; j++) {
            int hb = (fend + j) << 10;
            #pragma unroll
            for (int u = 0; u < 2; u++) {
                int p = tid + u*512;
                tailp[j * HOP + p] = sAcc[(hb + p) & (NFFT - 1)];
            }
        }
    } else {
        // final strip: hop 600 complete from ring (frames 597..599 are in-strip: h0=585)
        int j0 = (NFRM << 10);   // 614400
        #pragma unroll
        for (int u = 0; u < 2; u++) {
            int jj = j0 + tid + u*512;
            float2 v = sAcc[jj & (NFFT - 1)];
            int t = jj - PAD;
            float wi = d_wsuminv[jj];
            o0[t] = v.x * wi;
            o1[t] = v.y * wi;
        }
    }
}

// ---------------- boundary cleanup: out = (head[s] + tail[s-1]) * wsuminv ----------------
__global__ __launch_bounds__(256) void boundary_kernel(float* __restrict__ out) {
    int id = blockIdx.x * blockDim.x + threadIdx.x;
    const int total = NBATCH*NSRC * (NSTRIP - 1) * 3 * HOP;
    if (id >= total) return;
    int p  = id & (HOP - 1);
    int j  = (id >> 10) % 3;
    int sp = ((id >> 10) / 3) % (NSTRIP - 1);
    int ns = (id >> 10) / (3 * (NSTRIP - 1));
    int strip = sp + 1;                          // strips 1..NSTRIP-1
    int hop = strip * FOWN + j;
    float2 h = d_head[((size_t)(ns * NSTRIP + strip) * 3 + j) * HOP + p];
    float2 t2 = d_tail[((size_t)(ns * NSTRIP + strip - 1) * 3 + j) * HOP + p];
    int jj = (hop << 10) + p;
    int t = jj - PAD;
    if (t < 0 || t >= TLEN) return;
    float wi = d_wsuminv[jj];
    out[((size_t)ns * NCH + 0) * TLEN + t] = (h.x + t2.x) * wi;
    out[((size_t)ns * NCH + 1) * TLEN + t] = (h.y + t2.y) * wi;
}

// ---------------- launch ----------------
extern "C" void kernel_launch(void* const* d_in, const int* in_sizes, int n_in,
                              void* d_out, int out_size) {
    const float* audio = (const float*)d_in[0];
    const float* W     = (const float*)d_in[1];
    float* out = (float*)d_out;

    init_kernel<<<16, 256>>>();
    init2_kernel<<<(OUTLEN + 255) / 256, 256>>>();
    stft_kernel<<<NBATCH * NFRM, 512>>>(audio);
    wiener_g_kernel<<<dim3((NBINS + 31) / 32, NBATCH * NCHUNK, 20), 256>>>();
    wiener_coef_kernel<<<(NBATCH*NCHUNK*NBINS + 255) / 256, 256>>>(W);
    {
        size_t total = (size_t)NBATCH * NFRM * NBINS;
        wiener_apply_kernel<<<(unsigned)((total + 255) / 256), 256>>>();
    }
    istft_ola_kernel<<<NBATCH * NSRC * NSTRIP, 512>>>(out);
    {
        int total = NBATCH*NSRC * (NSTRIP - 1) * 3 * HOP;
        boundary_kernel<<<(total + 255) / 256, 256>>>(out);
    }
}

// round 15
// speedup vs baseline: 1.1837x; 1.1837x over previous
#include <cuda_runtime.h>
#include <math.h>

// ---------------- problem constants ----------------
#define NBATCH 2
#define NCH    2
#define NSRC   4
#define NFFT   4096
#define HOP    1024
#define NBINS  2049
#define NFRM   600
#define WINLEN 300
#define NCHUNK 2
#define TLEN   613376
#define PAD    2048
#define EPSV   1e-10f
#define SQEPS  1e-5f
#define OUTLEN (NFFT + HOP*(NFRM-1))   // 617472
#define NHOP   601
#define FOWN   17
#define NSTRIP 36

// exchange row strides (bank-conflict-free for float2/LDS.64, 512 cols)
#define ST1 514
#define ST2 520
#define SBUF (8*ST2)

// ---------------- device scratch ----------------
__device__ float2 d_rt[NBINS];
__device__ float  d_win[NFFT];
__device__ float  d_wsuminv[OUTLEN];
__device__ unsigned int d_maxsq[NBATCH*NCHUNK];
__device__ float4 d_X4[(size_t)NBATCH*NFRM*NBINS];             // (x0.re,x0.im,x1.re,x1.im)
__device__ float4 d_W[(size_t)NBATCH*NFRM*NBINS];              // ma*p*(w0,w1)
__device__ float  d_G[(size_t)NBATCH*NCHUNK*NBINS*4];          // raw G accumulators
__device__ float4 d_Gs[(size_t)NBATCH*NCHUNK*NBINS];           // scaled G
__device__ float  d_A[(size_t)NBATCH*NCHUNK*NBINS];            // sum of coefs
__device__ float  d_coef[(size_t)NBATCH*NCHUNK*NSRC*NBINS];    // per-source bin coef
// boundary handoff buffers: [ns][strip][3 hops][1024 samples], (ch0,ch1)
__device__ float2 d_head[(size_t)NBATCH*NSRC*NSTRIP*3*HOP];
__device__ float2 d_tail[(size_t)NBATCH*NSRC*NSTRIP*3*HOP];

__device__ __forceinline__ float2 cmul(float2 a, float2 b) {
    return make_float2(a.x*b.x - a.y*b.y, a.x*b.y + a.y*b.x);
}
__device__ __forceinline__ float2 cadd(float2 a, float2 b) { return make_float2(a.x+b.x, a.y+b.y); }
__device__ __forceinline__ float2 csub(float2 a, float2 b) { return make_float2(a.x-b.x, a.y-b.y); }

template<bool INV>
__device__ __forceinline__ float2 mul_pm_i(float2 d) {
    return INV ? make_float2(-d.y, d.x) : make_float2(d.y, -d.x);
}

// ---------------- init ----------------
__global__ void init_kernel() {
    int i = blockIdx.x * blockDim.x + threadIdx.x;
    if (i < NBINS) {
        double ang = -2.0 * M_PI * (double)i / (double)NFFT;
        d_rt[i] = make_float2((float)cos(ang), (float)sin(ang));
    }
    if (i < NFFT) {
        double w = 0.5 * (1.0 - cos(2.0 * M_PI * (double)i / (double)NFFT));
        d_win[i]  = (float)w;
    }
    if (i < NBATCH*NCHUNK) d_maxsq[i] = 0u;
}

// ---------------- init2: wsuminv (all-float) + zero G ----------------
__global__ void init2_kernel() {
    int i = blockIdx.x * blockDim.x + threadIdx.x;
    if (i < NBATCH*NCHUNK*NBINS*4) d_G[i] = 0.f;
    if (i >= OUTLEN) return;
    int fhi = min(NFRM - 1, i >> 10);
    int flo = max(0, (i - (NFFT - HOP)) >> 10);
    float wsum = 0.f;
    for (int f = flo; f <= fhi; f++) {
        float w = d_win[i - (f << 10)];
        wsum += w * w;
    }
    d_wsuminv[i] = 1.f / (wsum > 1e-11f ? wsum : 1.f);
}

// ---------------- radix-8 DFT in registers ----------------
template<bool INV>
__device__ __forceinline__ void dft8(const float2 a[8], float2 r[8]) {
    const float s = 0.70710678118654752440f;
    float2 t0 = cadd(a[0], a[4]);
    float2 t1 = csub(a[0], a[4]);
    float2 t2 = cadd(a[2], a[6]);
    float2 t3 = mul_pm_i<INV>(csub(a[2], a[6]));
    float2 E0 = cadd(t0, t2), E1 = cadd(t1, t3), E2 = csub(t0, t2), E3 = csub(t1, t3);
    float2 u0 = cadd(a[1], a[5]);
    float2 u1 = csub(a[1], a[5]);
    float2 u2 = cadd(a[3], a[7]);
    float2 u3 = mul_pm_i<INV>(csub(a[3], a[7]));
    float2 O0 = cadd(u0, u2), O1 = cadd(u1, u3), O2 = csub(u0, u2), O3 = csub(u1, u3);
    float2 O1t, O2t, O3t;
    if (!INV) {
        O1t = make_float2(s*(O1.x + O1.y), s*(O1.y - O1.x));
        O2t = make_float2(O2.y, -O2.x);
        O3t = make_float2(s*(O3.y - O3.x), -s*(O3.x + O3.y));
    } else {
        O1t = make_float2(s*(O1.x - O1.y), s*(O1.x + O1.y));
        O2t = make_float2(-O2.y, O2.x);
        O3t = make_float2(-s*(O3.x + O3.y), s*(O3.x - O3.y));
    }
    r[0] = cadd(E0, O0);  r[4] = csub(E0, O0);
    r[1] = cadd(E1, O1t); r[5] = csub(E1, O1t);
    r[2] = cadd(E2, O2t); r[6] = csub(E2, O2t);
    r[3] = cadd(E3, O3t); r[7] = csub(E3, O3t);
}

// product-tree twiddles (R13 version; regs are fine at 2 blocks/SM)
template<bool INV>
__device__ __forceinline__ void twiddle8(float2 r[8], int jm) {
    float2 w1 = d_rt[jm];
    if (INV) w1.y = -w1.y;
    float2 w2 = cmul(w1, w1);
    float2 w3 = cmul(w2, w1);
    float2 w4 = cmul(w2, w2);
    float2 w5 = cmul(w4, w1);
    float2 w6 = cmul(w4, w2);
    float2 w7 = cmul(w4, w3);
    r[1] = cmul(r[1], w1);
    r[2] = cmul(r[2], w2);
    r[3] = cmul(r[3], w3);
    r[4] = cmul(r[4], w4);
    r[5] = cmul(r[5], w5);
    r[6] = cmul(r[6], w6);
    r[7] = cmul(r[7], w7);
}

// ---------------- 4096-pt radix-8 Stockham: ping-pong buffers, 3 syncs ----------------
// Caller must ensure no thread is still reading sA from a previous call before
// the next call writes it (frame-end/staging sync).
template<bool INV>
__device__ void fft4096_reg(float2 a[8], float2* __restrict__ sA, float2* __restrict__ sB, int tid) {
    float2 r[8];
    // stage 1 -> sA (ST1)
    dft8<INV>(a, r);
    twiddle8<INV>(r, tid);
    #pragma unroll
    for (int q = 0; q < 8; q++) sA[q*ST1 + tid] = r[q];
    __syncthreads();
    #pragma unroll
    for (int q = 0; q < 8; q++) {
        int p = tid + q*512;
        a[q] = sA[(p & 7)*ST1 + (p >> 3)];
    }
    // stage 2 -> sB (ST2)
    dft8<INV>(a, r);
    twiddle8<INV>(r, tid - (tid & 7));
    #pragma unroll
    for (int q = 0; q < 8; q++) sB[q*ST2 + tid] = r[q];
    __syncthreads();
    #pragma unroll
    for (int q = 0; q < 8; q++) {
        int p = tid + q*512;
        int row = (p >> 3) & 7, col = ((p >> 6) << 3) | (p & 7);
        a[q] = sB[row*ST2 + col];
    }
    // stage 3 -> sA (ST2)
    dft8<INV>(a, r);
    twiddle8<INV>(r, tid - (tid & 63));
    #pragma unroll
    for (int q = 0; q < 8; q++) sA[q*ST2 + tid] = r[q];
    __syncthreads();
    #pragma unroll
    for (int q = 0; q < 8; q++) {
        int p = tid + q*512;
        int row = (p >> 6) & 7, col = ((p >> 9) << 6) | (p & 63);
        a[q] = sA[row*ST2 + col];
    }
    // stage 4: m=512, twiddles = 1
    dft8<INV>(a, r);
    #pragma unroll
    for (int q = 0; q < 8; q++) a[q] = r[q];
}

// ---------------- STFT: one block per (n,frame); both channels packed ----------------
__global__ __launch_bounds__(512) void stft_kernel(const float* __restrict__ audio) {
    __shared__ float2 sA[SBUF];
    __shared__ float2 sB[SBUF];
    __shared__ float red[512];
    int bid = blockIdx.x;                 // n*600 + f
    int f   = bid % NFRM;
    int n   = bid / NFRM;
    int tid = threadIdx.x;
    const float* a0 = audio + (size_t)(n*NCH + 0) * TLEN;
    const float* a1 = audio + (size_t)(n*NCH + 1) * TLEN;
    int base = f * HOP - PAD;

    float2 a[8];
    #pragma unroll
    for (int q = 0; q < 8; q++) {
        int t = tid + q*512;
        int j = base + t;
        if (j < 0) j = -j; else if (j >= TLEN) j = 2*TLEN - 2 - j;
        float w = d_win[t];
        a[q] = make_float2(a0[j] * w, a1[j] * w);
    }
    fft4096_reg<false>(a, sA, sB, tid);
    __syncthreads();   // stage-3 reads of sA done before restaging below

    #pragma unroll
    for (int q = 0; q < 8; q++) sA[tid + q*512] = a[q];
    __syncthreads();

    float4* out = d_X4 + ((size_t)n * NFRM + f) * NBINS;
    float lmax = 0.f;
    for (int k = tid; k < NBINS; k += 512) {
        int kb = (NFFT - k) & (NFFT - 1);
        float2 Zk = sA[k];
        float2 Zm = sA[kb];
        float x0r = 0.5f*(Zk.x + Zm.x), x0i = 0.5f*(Zk.y - Zm.y);
        float x1r = 0.5f*(Zk.y + Zm.y), x1i = 0.5f*(Zm.x - Zk.x);
        out[k] = make_float4(x0r, x0i, x1r, x1i);
        lmax = fmaxf(lmax, fmaxf(x0r*x0r + x0i*x0i, x1r*x1r + x1i*x1i));
    }
    red[tid] = lmax; __syncthreads();
    for (int s2 = 256; s2 > 0; s2 >>= 1) {
        if (tid < s2) red[tid] = fmaxf(red[tid], red[tid + s2]);
        __syncthreads();
    }
    if (tid == 0)
        atomicMax(&d_maxsq[n * NCHUNK + f / WINLEN], __float_as_uint(red[0]));
}

// ---------------- wiener pass A: raw spatial covariance G (t-split, atomic) ----------------
__global__ __launch_bounds__(256) void wiener_g_kernel() {
    __shared__ float sred[4][8][32];
    int nchunk = blockIdx.y;
    int seg = blockIdx.z;
    int n = nchunk >> 1, chunk = nchunk & 1;
    int tid = threadIdx.x;
    int bi = tid & 31, tg = tid >> 5;
    int b = blockIdx.x * 32 + bi;
    bool valid = (b < NBINS);
    int bc = valid ? b : 0;

    const float4* xp = d_X4 + ((size_t)n * NFRM + chunk*WINLEN + seg*15) * NBINS + bc;

    float g00 = 0.f, g11 = 0.f, g01r = 0.f, g01i = 0.f;
    for (int t = tg; t < 15; t += 8) {
        float4 v = xp[(size_t)t * NBINS];
        g00 += v.x*v.x + v.y*v.y;
        g11 += v.z*v.z + v.w*v.w;
        g01r += v.x*v.z + v.y*v.w;
        g01i += v.y*v.z - v.x*v.w;
    }
    sred[0][tg][bi] = g00; sred[1][tg][bi] = g11;
    sred[2][tg][bi] = g01r; sred[3][tg][bi] = g01i;
    __syncthreads();
    if (tg == 0 && valid) {
        g00 = g11 = g01r = g01i = 0.f;
        #pragma unroll
        for (int k = 0; k < 8; k++) {
            g00 += sred[0][k][bi]; g11 += sred[1][k][bi];
            g01r += sred[2][k][bi]; g01i += sred[3][k][bi];
        }
        float* gp = d_G + ((size_t)nchunk * NBINS + b) * 4;
        atomicAdd(gp + 0, g00);
        atomicAdd(gp + 1, g11);
        atomicAdd(gp + 2, g01r);
        atomicAdd(gp + 3, g01i);
    }
}

// ---------------- wiener pass B: per-bin coefs ----------------
__global__ void wiener_coef_kernel(const float* __restrict__ W) {
    int id = blockIdx.x * blockDim.x + threadIdx.x;
    if (id >= NBATCH*NCHUNK*NBINS) return;
    int b = id % NBINS;
    int nchunk = id / NBINS;
    float maxsq = __uint_as_float(d_maxsq[nchunk]);
    float ma = fmaxf(1.f, sqrtf(maxsq) * 0.1f);
    float inv_ma2 = 1.f / (ma * ma);
    const float* gp = d_G + (size_t)id * 4;
    float g00 = gp[0] * inv_ma2;
    float g11 = gp[1] * inv_ma2;
    float g01r = gp[2] * inv_ma2;
    float g01i = gp[3] * inv_ma2;
    float P = 0.5f * (g00 + g11);
    float A = 0.f;
    #pragma unroll
    for (int s = 0; s < NSRC; s++) {
        float m  = 1.f / (1.f + expf(-W[s * NBINS + b]));
        float m2 = m * m;
        float c = (m2 * m2) / (EPSV + m2 * P);
        A += c;
        d_coef[((size_t)(nchunk * NSRC + s)) * NBINS + b] = c;
    }
    d_Gs[id] = make_float4(g00, g11, g01r, g01i);
    d_A[id] = A;
}

// ---------------- wiener pass C: apply per (n,t,b) ----------------
__global__ __launch_bounds__(256) void wiener_apply_kernel() {
    size_t id = (size_t)blockIdx.x * blockDim.x + threadIdx.x;
    const size_t total = (size_t)NBATCH * NFRM * NBINS;
    if (id >= total) return;
    int b = (int)(id % NBINS);
    int nf = (int)(id / NBINS);
    int f = nf % NFRM;
    int n = nf / NFRM;
    int nchunk = n * NCHUNK + (f >= WINLEN ? 1 : 0);

    float maxsq = __uint_as_float(d_maxsq[nchunk]);
    float ma = fmaxf(1.f, sqrtf(maxsq) * 0.1f);
    float inv_ma = 1.f / ma;

    float4 v = d_X4[id];
    float4 g4 = d_Gs[(size_t)nchunk * NBINS + b];
    float A = d_A[(size_t)nchunk * NBINS + b];
    float g00 = g4.x, g11 = g4.y, g01r = g4.z, g01i = g4.w;

    float2 x0 = make_float2(v.x*inv_ma, v.y*inv_ma);
    float2 x1 = make_float2(v.z*inv_ma, v.w*inv_ma);
    float p = 0.5f * (x0.x*x0.x + x0.y*x0.y + x1.x*x1.x + x1.y*x1.y);
    float bt = p * A;
    float c00 = SQEPS + bt * g00;
    float c11 = SQEPS + bt * g11;
    float c01r = bt * g01r, c01i = bt * g01i;
    float det = c00 * c11 - (c01r*c01r + c01i*c01i);
    float idet = 1.f / det;
    float2 u0, u1;
    u0.x = idet * (c11 * x0.x - (c01r * x1.x - c01i * x1.y));
    u0.y = idet * (c11 * x0.y - (c01r * x1.y + c01i * x1.x));
    u1.x = idet * ((-c01r * x0.x - c01i * x0.y) + c00 * x1.x);
    u1.y = idet * (( c01i * x0.x - c01r * x0.y) + c00 * x1.y);
    float2 w0, w1;
    w0.x = g00 * u0.x + g01r * u1.x - g01i * u1.y;
    w0.y = g00 * u0.y + g01r * u1.y + g01i * u1.x;
    w1.x = g01r * u0.x + g01i * u0.y + g11 * u1.x;
    w1.y = g01r * u0.y - g01i * u0.x + g11 * u1.y;
    float sc = ma * p;
    d_W[id] = make_float4(sc*w0.x, sc*w0.y, sc*w1.x, sc*w1.y);
}

// ---------------- fused iSTFT + OLA, no halo (boundary handoff), ping-pong FFT ----------------
__global__ __launch_bounds__(512, 2) void istft_ola_kernel(float* __restrict__ out) {
    __shared__ float2 sA[SBUF];
    __shared__ float2 sB[SBUF];
    __shared__ float2 sAcc[NFFT];
    int bid = blockIdx.x;          // ns*NSTRIP + strip
    int strip = bid % NSTRIP;
    int ns = bid / NSTRIP;         // n*4 + s
    int n = ns >> 2;
    int s = ns & 3;
    int tid = threadIdx.x;

    int h0 = strip * FOWN;
    int fend = min(NFRM, h0 + FOWN);

    float* o0 = out + ((size_t)ns * NCH + 0) * TLEN;
    float* o1 = out + ((size_t)ns * NCH + 1) * TLEN;
    float2* headp = d_head + ((size_t)(ns * NSTRIP + strip) * 3) * HOP;
    float2* tailp = d_tail + ((size_t)(ns * NSTRIP + strip) * 3) * HOP;

    #pragma unroll
    for (int q = 0; q < 8; q++) sAcc[tid + q*512] = make_float2(0.f, 0.f);
    __syncthreads();

    const float inv_n = 1.f / (float)NFFT;

    for (int f = h0; f < fend; f++) {
        int chunk = f / WINLEN;
        const float4* Wrow = d_W + ((size_t)n * NFRM + f) * NBINS;
        const float*  crow = d_coef + ((size_t)((n*NCHUNK + chunk) * NSRC + s)) * NBINS;

        float2 a[8];
        #pragma unroll
        for (int q = 0; q < 8; q++) {
            int j = tid + q*512;
            int k = (j <= 2048) ? j : (NFFT - j);
            float4 w4 = Wrow[k];
            float cc  = crow[k];
            if (j <= 2048)
                a[q] = make_float2(cc * (w4.x - w4.w), cc * (w4.y + w4.z));
            else
                a[q] = make_float2(cc * (w4.x + w4.w), cc * (w4.z - w4.y));
        }
        fft4096_reg<true>(a, sA, sB, tid);

        int fb = (f << 10);
        bool head = (f - h0 < 3) && (h0 > 0);   // partial hop (prev strip contributes)
        // finalize hop f: ring + in-register a[0],a[1]; zero slots
        #pragma unroll
        for (int u = 0; u < 2; u++) {
            int p = tid + u*512;
            int jj = fb + p;
            int slot = jj & (NFFT - 1);
            float w = inv_n * d_win[p];
            float2 v = sAcc[slot];
            v.x += a[u].x * w;
            v.y += a[u].y * w;
            sAcc[slot] = make_float2(0.f, 0.f);
            if (head) {
                headp[(f - h0) * HOP + p] = v;
            } else {
                int t = jj - PAD;
                if (t >= 0 && t < TLEN) {
                    float wi = d_wsuminv[jj];
                    o0[t] = v.x * wi;
                    o1[t] = v.y * wi;
                }
            }
        }
        // tail accumulate (hops f+1..f+3): disjoint slots from finalize
        #pragma unroll
        for (int q = 2; q < 8; q++) {
            int p = tid + q*512;
            int slot = (fb + p) & (NFFT - 1);
            float w = inv_n * d_win[p];
            float2 acc = sAcc[slot];
            sAcc[slot] = make_float2(acc.x + a[q].x * w, acc.y + a[q].y * w);
        }
        __syncthreads();   // also orders sA stage-3 reads before next frame's stage-1 writes
    }

    if (fend < NFRM) {
        // hand off ring tail (partials for hops fend..fend+2) to next strip
        #pragma unroll
        for (int j = 0; j < 3; j++) {
            int hb = (fend + j) << 10;
            #pragma unroll
            for (int u = 0; u < 2; u++) {
                int p = tid + u*512;
                tailp[j * HOP + p] = sAcc[(hb + p) & (NFFT - 1)];
            }
        }
    } else {
        // final strip: hop 600 complete from ring (frames 597..599 in-strip)
        int j0 = (NFRM << 10);   // 614400
        #pragma unroll
        for (int u = 0; u < 2; u++) {
            int jj = j0 + tid + u*512;
            float2 v = sAcc[jj & (NFFT - 1)];
            int t = jj - PAD;
            float wi = d_wsuminv[jj];
            o0[t] = v.x * wi;
            o1[t] = v.y * wi;
        }
    }
}

// ---------------- boundary cleanup: out = (head[s] + tail[s-1]) * wsuminv ----------------
__global__ __launch_bounds__(256) void boundary_kernel(float* __restrict__ out) {
    int id = blockIdx.x * blockDim.x + threadIdx.x;
    const int total = NBATCH*NSRC * (NSTRIP - 1) * 3 * HOP;
    if (id >= total) return;
    int p  = id & (HOP - 1);
    int j  = (id >> 10) % 3;
    int sp = ((id >> 10) / 3) % (NSTRIP - 1);
    int ns = (id >> 10) / (3 * (NSTRIP - 1));
    int strip = sp + 1;                          // strips 1..NSTRIP-1
    int hop = strip * FOWN + j;
    float2 h = d_head[((size_t)(ns * NSTRIP + strip) * 3 + j) * HOP + p];
    float2 t2 = d_tail[((size_t)(ns * NSTRIP + strip - 1) * 3 + j) * HOP + p];
    int jj = (hop << 10) + p;
    int t = jj - PAD;
    if (t < 0 || t >= TLEN) return;
    float wi = d_wsuminv[jj];
    out[((size_t)ns * NCH + 0) * TLEN + t] = (h.x + t2.x) * wi;
    out[((size_t)ns * NCH + 1) * TLEN + t] = (h.y + t2.y) * wi;
}

// ---------------- launch ----------------
extern "C" void kernel_launch(void* const* d_in, const int* in_sizes, int n_in,
                              void* d_out, int out_size) {
    const float* audio = (const float*)d_in[0];
    const float* W     = (const float*)d_in[1];
    float* out = (float*)d_out;

    init_kernel<<<16, 256>>>();
    init2_kernel<<<(OUTLEN + 255) / 256, 256>>>();
    stft_kernel<<<NBATCH * NFRM, 512>>>(audio);
    wiener_g_kernel<<<dim3((NBINS + 31) / 32, NBATCH * NCHUNK, 20), 256>>>();
    wiener_coef_kernel<<<(NBATCH*NCHUNK*NBINS + 255) / 256, 256>>>(W);
    {
        size_t total = (size_t)NBATCH * NFRM * NBINS;
        wiener_apply_kernel<<<(unsigned)((total + 255) / 256), 256>>>();
    }
    istft_ola_kernel<<<NBATCH * NSRC * NSTRIP, 512>>>(out);
    {
        int total = NBATCH*NSRC * (NSTRIP - 1) * 3 * HOP;
        boundary_kernel<<<(total + 255) / 256, 256>>>(out);
    }
}

// round 16
// speedup vs baseline: 1.2103x; 1.0225x over previous
#include <cuda_runtime.h>
#include <math.h>

// ---------------- problem constants ----------------
#define NBATCH 2
#define NCH    2
#define NSRC   4
#define NFFT   4096
#define HOP    1024
#define NBINS  2049
#define NFRM   600
#define WINLEN 300
#define NCHUNK 2
#define TLEN   613376
#define PAD    2048
#define EPSV   1e-10f
#define SQEPS  1e-5f
#define OUTLEN (NFFT + HOP*(NFRM-1))   // 617472
#define NHOP   601
#define FOWN   17
#define NSTRIP 36

// exchange row strides (bank-conflict-free for float2/LDS.64, 512 cols)
#define ST1 514
#define ST2 520
#define SBUF (8*ST2)

// ---------------- device scratch ----------------
__device__ float2 d_rt[NBINS];
__device__ float  d_win[NFFT];
__device__ float  d_wsuminv[OUTLEN];
__device__ unsigned int d_maxsq[NBATCH*NCHUNK];
__device__ float4 d_X4[(size_t)NBATCH*NFRM*NBINS];             // (x0.re,x0.im,x1.re,x1.im)
__device__ float4 d_W[(size_t)NBATCH*NFRM*NBINS];              // ma*p*(w0,w1)
__device__ float  d_G[(size_t)NBATCH*NCHUNK*NBINS*4];          // raw G accumulators
__device__ float4 d_Gs[(size_t)NBATCH*NCHUNK*NBINS];           // scaled G
__device__ float  d_A[(size_t)NBATCH*NCHUNK*NBINS];            // sum of coefs
__device__ float  d_coef[(size_t)NBATCH*NCHUNK*NSRC*NBINS];    // per-source bin coef
// boundary handoff buffers: [ns][strip][3 hops][1024 samples], (ch0,ch1)
__device__ float2 d_head[(size_t)NBATCH*NSRC*NSTRIP*3*HOP];
__device__ float2 d_tail[(size_t)NBATCH*NSRC*NSTRIP*3*HOP];

__device__ __forceinline__ float2 cmul(float2 a, float2 b) {
    return make_float2(a.x*b.x - a.y*b.y, a.x*b.y + a.y*b.x);
}
__device__ __forceinline__ float2 cadd(float2 a, float2 b) { return make_float2(a.x+b.x, a.y+b.y); }
__device__ __forceinline__ float2 csub(float2 a, float2 b) { return make_float2(a.x-b.x, a.y-b.y); }

template<bool INV>
__device__ __forceinline__ float2 mul_pm_i(float2 d) {
    return INV ? make_float2(-d.y, d.x) : make_float2(d.y, -d.x);
}

// ---------------- init ----------------
__global__ void init_kernel() {
    int i = blockIdx.x * blockDim.x + threadIdx.x;
    if (i < NBINS) {
        double ang = -2.0 * M_PI * (double)i / (double)NFFT;
        d_rt[i] = make_float2((float)cos(ang), (float)sin(ang));
    }
    if (i < NFFT) {
        double w = 0.5 * (1.0 - cos(2.0 * M_PI * (double)i / (double)NFFT));
        d_win[i]  = (float)w;
    }
    if (i < NBATCH*NCHUNK) d_maxsq[i] = 0u;
}

// ---------------- init2: wsuminv (all-float) + zero G ----------------
__global__ void init2_kernel() {
    int i = blockIdx.x * blockDim.x + threadIdx.x;
    if (i < NBATCH*NCHUNK*NBINS*4) d_G[i] = 0.f;
    if (i >= OUTLEN) return;
    int fhi = min(NFRM - 1, i >> 10);
    int flo = max(0, (i - (NFFT - HOP)) >> 10);
    float wsum = 0.f;
    for (int f = flo; f <= fhi; f++) {
        float w = d_win[i - (f << 10)];
        wsum += w * w;
    }
    d_wsuminv[i] = 1.f / (wsum > 1e-11f ? wsum : 1.f);
}

// ---------------- radix-8 DFT in registers ----------------
template<bool INV>
__device__ __forceinline__ void dft8(const float2 a[8], float2 r[8]) {
    const float s = 0.70710678118654752440f;
    float2 t0 = cadd(a[0], a[4]);
    float2 t1 = csub(a[0], a[4]);
    float2 t2 = cadd(a[2], a[6]);
    float2 t3 = mul_pm_i<INV>(csub(a[2], a[6]));
    float2 E0 = cadd(t0, t2), E1 = cadd(t1, t3), E2 = csub(t0, t2), E3 = csub(t1, t3);
    float2 u0 = cadd(a[1], a[5]);
    float2 u1 = csub(a[1], a[5]);
    float2 u2 = cadd(a[3], a[7]);
    float2 u3 = mul_pm_i<INV>(csub(a[3], a[7]));
    float2 O0 = cadd(u0, u2), O1 = cadd(u1, u3), O2 = csub(u0, u2), O3 = csub(u1, u3);
    float2 O1t, O2t, O3t;
    if (!INV) {
        O1t = make_float2(s*(O1.x + O1.y), s*(O1.y - O1.x));
        O2t = make_float2(O2.y, -O2.x);
        O3t = make_float2(s*(O3.y - O3.x), -s*(O3.x + O3.y));
    } else {
        O1t = make_float2(s*(O1.x - O1.y), s*(O1.x + O1.y));
        O2t = make_float2(-O2.y, O2.x);
        O3t = make_float2(-s*(O3.x + O3.y), s*(O3.x - O3.y));
    }
    r[0] = cadd(E0, O0);  r[4] = csub(E0, O0);
    r[1] = cadd(E1, O1t); r[5] = csub(E1, O1t);
    r[2] = cadd(E2, O2t); r[6] = csub(E2, O2t);
    r[3] = cadd(E3, O3t); r[7] = csub(E3, O3t);
}

// product-tree twiddles
template<bool INV>
__device__ __forceinline__ void twiddle8(float2 r[8], int jm) {
    float2 w1 = d_rt[jm];
    if (INV) w1.y = -w1.y;
    float2 w2 = cmul(w1, w1);
    float2 w3 = cmul(w2, w1);
    float2 w4 = cmul(w2, w2);
    float2 w5 = cmul(w4, w1);
    float2 w6 = cmul(w4, w2);
    float2 w7 = cmul(w4, w3);
    r[1] = cmul(r[1], w1);
    r[2] = cmul(r[2], w2);
    r[3] = cmul(r[3], w3);
    r[4] = cmul(r[4], w4);
    r[5] = cmul(r[5], w5);
    r[6] = cmul(r[6], w6);
    r[7] = cmul(r[7], w7);
}

// ---------------- 4096-pt radix-8 Stockham, single buffer (6 syncs) — stft ----------------
template<bool INV>
__device__ void fft4096_reg(float2 a[8], float2* __restrict__ sC, int tid) {
    float2 r[8];
    dft8<INV>(a, r);
    twiddle8<INV>(r, tid);
    #pragma unroll
    for (int q = 0; q < 8; q++) sC[q*ST1 + tid] = r[q];
    __syncthreads();
    #pragma unroll
    for (int q = 0; q < 8; q++) {
        int p = tid + q*512;
        a[q] = sC[(p & 7)*ST1 + (p >> 3)];
    }
    __syncthreads();
    dft8<INV>(a, r);
    twiddle8<INV>(r, tid - (tid & 7));
    #pragma unroll
    for (int q = 0; q < 8; q++) sC[q*ST2 + tid] = r[q];
    __syncthreads();
    #pragma unroll
    for (int q = 0; q < 8; q++) {
        int p = tid + q*512;
        int row = (p >> 3) & 7, col = ((p >> 6) << 3) | (p & 7);
        a[q] = sC[row*ST2 + col];
    }
    __syncthreads();
    dft8<INV>(a, r);
    twiddle8<INV>(r, tid - (tid & 63));
    #pragma unroll
    for (int q = 0; q < 8; q++) sC[q*ST2 + tid] = r[q];
    __syncthreads();
    #pragma unroll
    for (int q = 0; q < 8; q++) {
        int p = tid + q*512;
        int row = (p >> 6) & 7, col = ((p >> 9) << 6) | (p & 63);
        a[q] = sC[row*ST2 + col];
    }
    __syncthreads();
    dft8<INV>(a, r);
    #pragma unroll
    for (int q = 0; q < 8; q++) a[q] = r[q];
}

// ---------------- 4096-pt radix-8 Stockham, ping-pong (3 syncs) — istft ----------------
// Caller must sync before next call (re-use of sA).
template<bool INV>
__device__ void fft4096_pp(float2 a[8], float2* __restrict__ sA, float2* __restrict__ sB, int tid) {
    float2 r[8];
    dft8<INV>(a, r);
    twiddle8<INV>(r, tid);
    #pragma unroll
    for (int q = 0; q < 8; q++) sA[q*ST1 + tid] = r[q];
    __syncthreads();
    #pragma unroll
    for (int q = 0; q < 8; q++) {
        int p = tid + q*512;
        a[q] = sA[(p & 7)*ST1 + (p >> 3)];
    }
    dft8<INV>(a, r);
    twiddle8<INV>(r, tid - (tid & 7));
    #pragma unroll
    for (int q = 0; q < 8; q++) sB[q*ST2 + tid] = r[q];
    __syncthreads();
    #pragma unroll
    for (int q = 0; q < 8; q++) {
        int p = tid + q*512;
        int row = (p >> 3) & 7, col = ((p >> 6) << 3) | (p & 7);
        a[q] = sB[row*ST2 + col];
    }
    dft8<INV>(a, r);
    twiddle8<INV>(r, tid - (tid & 63));
    #pragma unroll
    for (int q = 0; q < 8; q++) sA[q*ST2 + tid] = r[q];
    __syncthreads();
    #pragma unroll
    for (int q = 0; q < 8; q++) {
        int p = tid + q*512;
        int row = (p >> 6) & 7, col = ((p >> 9) << 6) | (p & 63);
        a[q] = sA[row*ST2 + col];
    }
    dft8<INV>(a, r);
    #pragma unroll
    for (int q = 0; q < 8; q++) a[q] = r[q];
}

// ---------------- STFT: one block per (n,frame); both channels packed ----------------
__global__ __launch_bounds__(512) void stft_kernel(const float* __restrict__ audio) {
    __shared__ float2 sC[SBUF];
    __shared__ float red[512];
    int bid = blockIdx.x;                 // n*600 + f
    int f   = bid % NFRM;
    int n   = bid / NFRM;
    int tid = threadIdx.x;
    const float* a0 = audio + (size_t)(n*NCH + 0) * TLEN;
    const float* a1 = audio + (size_t)(n*NCH + 1) * TLEN;
    int base = f * HOP - PAD;

    float2 a[8];
    #pragma unroll
    for (int q = 0; q < 8; q++) {
        int t = tid + q*512;
        int j = base + t;
        if (j < 0) j = -j; else if (j >= TLEN) j = 2*TLEN - 2 - j;
        float w = d_win[t];
        a[q] = make_float2(a0[j] * w, a1[j] * w);
    }
    fft4096_reg<false>(a, sC, tid);

    #pragma unroll
    for (int q = 0; q < 8; q++) sC[tid + q*512] = a[q];
    __syncthreads();

    float4* out = d_X4 + ((size_t)n * NFRM + f) * NBINS;
    float lmax = 0.f;
    for (int k = tid; k < NBINS; k += 512) {
        int kb = (NFFT - k) & (NFFT - 1);
        float2 Zk = sC[k];
        float2 Zm = sC[kb];
        float x0r = 0.5f*(Zk.x + Zm.x), x0i = 0.5f*(Zk.y - Zm.y);
        float x1r = 0.5f*(Zk.y + Zm.y), x1i = 0.5f*(Zm.x - Zk.x);
        out[k] = make_float4(x0r, x0i, x1r, x1i);
        lmax = fmaxf(lmax, fmaxf(x0r*x0r + x0i*x0i, x1r*x1r + x1i*x1i));
    }
    red[tid] = lmax; __syncthreads();
    for (int s2 = 256; s2 > 0; s2 >>= 1) {
        if (tid < s2) red[tid] = fmaxf(red[tid], red[tid + s2]);
        __syncthreads();
    }
    if (tid == 0)
        atomicMax(&d_maxsq[n * NCHUNK + f / WINLEN], __float_as_uint(red[0]));
}

// ---------------- wiener pass A: raw spatial covariance G (t-split, atomic) ----------------
__global__ __launch_bounds__(256) void wiener_g_kernel() {
    __shared__ float sred[4][8][32];
    int nchunk = blockIdx.y;
    int seg = blockIdx.z;
    int n = nchunk >> 1, chunk = nchunk & 1;
    int tid = threadIdx.x;
    int bi = tid & 31, tg = tid >> 5;
    int b = blockIdx.x * 32 + bi;
    bool valid = (b < NBINS);
    int bc = valid ? b : 0;

    const float4* xp = d_X4 + ((size_t)n * NFRM + chunk*WINLEN + seg*15) * NBINS + bc;

    float g00 = 0.f, g11 = 0.f, g01r = 0.f, g01i = 0.f;
    for (int t = tg; t < 15; t += 8) {
        float4 v = xp[(size_t)t * NBINS];
        g00 += v.x*v.x + v.y*v.y;
        g11 += v.z*v.z + v.w*v.w;
        g01r += v.x*v.z + v.y*v.w;
        g01i += v.y*v.z - v.x*v.w;
    }
    sred[0][tg][bi] = g00; sred[1][tg][bi] = g11;
    sred[2][tg][bi] = g01r; sred[3][tg][bi] = g01i;
    __syncthreads();
    if (tg == 0 && valid) {
        g00 = g11 = g01r = g01i = 0.f;
        #pragma unroll
        for (int k = 0; k < 8; k++) {
            g00 += sred[0][k][bi]; g11 += sred[1][k][bi];
            g01r += sred[2][k][bi]; g01i += sred[3][k][bi];
        }
        float* gp = d_G + ((size_t)nchunk * NBINS + b) * 4;
        atomicAdd(gp + 0, g00);
        atomicAdd(gp + 1, g11);
        atomicAdd(gp + 2, g01r);
        atomicAdd(gp + 3, g01i);
    }
}

// ---------------- wiener pass B: per-bin coefs ----------------
__global__ void wiener_coef_kernel(const float* __restrict__ W) {
    int id = blockIdx.x * blockDim.x + threadIdx.x;
    if (id >= NBATCH*NCHUNK*NBINS) return;
    int b = id % NBINS;
    int nchunk = id / NBINS;
    float maxsq = __uint_as_float(d_maxsq[nchunk]);
    float ma = fmaxf(1.f, sqrtf(maxsq) * 0.1f);
    float inv_ma2 = 1.f / (ma * ma);
    const float* gp = d_G + (size_t)id * 4;
    float g00 = gp[0] * inv_ma2;
    float g11 = gp[1] * inv_ma2;
    float g01r = gp[2] * inv_ma2;
    float g01i = gp[3] * inv_ma2;
    float P = 0.5f * (g00 + g11);
    float A = 0.f;
    #pragma unroll
    for (int s = 0; s < NSRC; s++) {
        float m  = 1.f / (1.f + expf(-W[s * NBINS + b]));
        float m2 = m * m;
        float c = (m2 * m2) / (EPSV + m2 * P);
        A += c;
        d_coef[((size_t)(nchunk * NSRC + s)) * NBINS + b] = c;
    }
    d_Gs[id] = make_float4(g00, g11, g01r, g01i);
    d_A[id] = A;
}

// ---------------- wiener pass C: apply per (n,t,b) ----------------
__global__ __launch_bounds__(256) void wiener_apply_kernel() {
    size_t id = (size_t)blockIdx.x * blockDim.x + threadIdx.x;
    const size_t total = (size_t)NBATCH * NFRM * NBINS;
    if (id >= total) return;
    int b = (int)(id % NBINS);
    int nf = (int)(id / NBINS);
    int f = nf % NFRM;
    int n = nf / NFRM;
    int nchunk = n * NCHUNK + (f >= WINLEN ? 1 : 0);

    float maxsq = __uint_as_float(d_maxsq[nchunk]);
    float ma = fmaxf(1.f, sqrtf(maxsq) * 0.1f);
    float inv_ma = 1.f / ma;

    float4 v = d_X4[id];
    float4 g4 = d_Gs[(size_t)nchunk * NBINS + b];
    float A = d_A[(size_t)nchunk * NBINS + b];
    float g00 = g4.x, g11 = g4.y, g01r = g4.z, g01i = g4.w;

    float2 x0 = make_float2(v.x*inv_ma, v.y*inv_ma);
    float2 x1 = make_float2(v.z*inv_ma, v.w*inv_ma);
    float p = 0.5f * (x0.x*x0.x + x0.y*x0.y + x1.x*x1.x + x1.y*x1.y);
    float bt = p * A;
    float c00 = SQEPS + bt * g00;
    float c11 = SQEPS + bt * g11;
    float c01r = bt * g01r, c01i = bt * g01i;
    float det = c00 * c11 - (c01r*c01r + c01i*c01i);
    float idet = 1.f / det;
    float2 u0, u1;
    u0.x = idet * (c11 * x0.x - (c01r * x1.x - c01i * x1.y));
    u0.y = idet * (c11 * x0.y - (c01r * x1.y + c01i * x1.x));
    u1.x = idet * ((-c01r * x0.x - c01i * x0.y) + c00 * x1.x);
    u1.y = idet * (( c01i * x0.x - c01r * x0.y) + c00 * x1.y);
    float2 w0, w1;
    w0.x = g00 * u0.x + g01r * u1.x - g01i * u1.y;
    w0.y = g00 * u0.y + g01r * u1.y + g01i * u1.x;
    w1.x = g01r * u0.x + g01i * u0.y + g11 * u1.x;
    w1.y = g01r * u0.y - g01i * u0.x + g11 * u1.y;
    float sc = ma * p;
    d_W[id] = make_float4(sc*w0.x, sc*w0.y, sc*w1.x, sc*w1.y);
}

// ---------------- fused iSTFT + OLA, no halo (boundary handoff), ping-pong FFT ----------------
__global__ __launch_bounds__(512, 2) void istft_ola_kernel(float* __restrict__ out) {
    __shared__ float2 sA[SBUF];
    __shared__ float2 sB[SBUF];
    __shared__ float2 sAcc[NFFT];
    int bid = blockIdx.x;          // ns*NSTRIP + strip
    int strip = bid % NSTRIP;
    int ns = bid / NSTRIP;         // n*4 + s
    int n = ns >> 2;
    int s = ns & 3;
    int tid = threadIdx.x;

    int h0 = strip * FOWN;
    int fend = min(NFRM, h0 + FOWN);

    float* o0 = out + ((size_t)ns * NCH + 0) * TLEN;
    float* o1 = out + ((size_t)ns * NCH + 1) * TLEN;
    float2* headp = d_head + ((size_t)(ns * NSTRIP + strip) * 3) * HOP;
    float2* tailp = d_tail + ((size_t)(ns * NSTRIP + strip) * 3) * HOP;

    #pragma unroll
    for (int q = 0; q < 8; q++) sAcc[tid + q*512] = make_float2(0.f, 0.f);
    __syncthreads();

    const float inv_n = 1.f / (float)NFFT;

    for (int f = h0; f < fend; f++) {
        int chunk = f / WINLEN;
        const float4* Wrow = d_W + ((size_t)n * NFRM + f) * NBINS;
        const float*  crow = d_coef + ((size_t)((n*NCHUNK + chunk) * NSRC + s)) * NBINS;

        float2 a[8];
        #pragma unroll
        for (int q = 0; q < 8; q++) {
            int j = tid + q*512;
            int k = (j <= 2048) ? j : (NFFT - j);
            float4 w4 = Wrow[k];
            float cc  = crow[k];
            if (j <= 2048)
                a[q] = make_float2(cc * (w4.x - w4.w), cc * (w4.y + w4.z));
            else
                a[q] = make_float2(cc * (w4.x + w4.w), cc * (w4.z - w4.y));
        }
        fft4096_pp<true>(a, sA, sB, tid);

        int fb = (f << 10);
        bool head = (f - h0 < 3) && (h0 > 0);   // partial hop (prev strip contributes)
        // finalize hop f: ring + in-register a[0],a[1]; zero slots
        #pragma unroll
        for (int u = 0; u < 2; u++) {
            int p = tid + u*512;
            int jj = fb + p;
            int slot = jj & (NFFT - 1);
            float w = inv_n * d_win[p];
            float2 v = sAcc[slot];
            v.x += a[u].x * w;
            v.y += a[u].y * w;
            sAcc[slot] = make_float2(0.f, 0.f);
            if (head) {
                headp[(f - h0) * HOP + p] = v;
            } else {
                int t = jj - PAD;
                if (t >= 0 && t < TLEN) {
                    float wi = d_wsuminv[jj];
                    o0[t] = v.x * wi;
                    o1[t] = v.y * wi;
                }
            }
        }
        // tail accumulate (hops f+1..f+3): disjoint slots from finalize
        #pragma unroll
        for (int q = 2; q < 8; q++) {
            int p = tid + q*512;
            int slot = (fb + p) & (NFFT - 1);
            float w = inv_n * d_win[p];
            float2 acc = sAcc[slot];
            sAcc[slot] = make_float2(acc.x + a[q].x * w, acc.y + a[q].y * w);
        }
        __syncthreads();   // orders ring RMW and sA stage-3 reads before next frame
    }

    if (fend < NFRM) {
        // hand off ring tail (partials for hops fend..fend+2) to next strip
        #pragma unroll
        for (int j = 0; j < 3; j++) {
            int hb = (fend + j) << 10;
            #pragma unroll
            for (int u = 0; u < 2; u++) {
                int p = tid + u*512;
                tailp[j * HOP + p] = sAcc[(hb + p) & (NFFT - 1)];
            }
        }
    } else {
        // final strip: hop 600 complete from ring (frames 597..599 in-strip)
        int j0 = (NFRM << 10);   // 614400
        #pragma unroll
        for (int u = 0; u < 2; u++) {
            int jj = j0 + tid + u*512;
            float2 v = sAcc[jj & (NFFT - 1)];
            int t = jj - PAD;
            float wi = d_wsuminv[jj];
            o0[t] = v.x * wi;
            o1[t] = v.y * wi;
        }
    }
}

// ---------------- boundary cleanup: out = (head[s] + tail[s-1]) * wsuminv ----------------
__global__ __launch_bounds__(256) void boundary_kernel(float* __restrict__ out) {
    int id = blockIdx.x * blockDim.x + threadIdx.x;
    const int total = NBATCH*NSRC * (NSTRIP - 1) * 3 * HOP;
    if (id >= total) return;
    int p  = id & (HOP - 1);
    int j  = (id >> 10) % 3;
    int sp = ((id >> 10) / 3) % (NSTRIP - 1);
    int ns = (id >> 10) / (3 * (NSTRIP - 1));
    int strip = sp + 1;                          // strips 1..NSTRIP-1
    int hop = strip * FOWN + j;
    float2 h = d_head[((size_t)(ns * NSTRIP + strip) * 3 + j) * HOP + p];
    float2 t2 = d_tail[((size_t)(ns * NSTRIP + strip - 1) * 3 + j) * HOP + p];
    int jj = (hop << 10) + p;
    int t = jj - PAD;
    if (t < 0 || t >= TLEN) return;
    float wi = d_wsuminv[jj];
    out[((size_t)ns * NCH + 0) * TLEN + t] = (h.x + t2.x) * wi;
    out[((size_t)ns * NCH + 1) * TLEN + t] = (h.y + t2.y) * wi;
}

// ---------------- launch ----------------
extern "C" void kernel_launch(void* const* d_in, const int* in_sizes, int n_in,
                              void* d_out, int out_size) {
    const float* audio = (const float*)d_in[0];
    const float* W     = (const float*)d_in[1];
    float* out = (float*)d_out;

    init_kernel<<<16, 256>>>();
    init2_kernel<<<(OUTLEN + 255) / 256, 256>>>();
    stft_kernel<<<NBATCH * NFRM, 512>>>(audio);
    wiener_g_kernel<<<dim3((NBINS + 31) / 32, NBATCH * NCHUNK, 20), 256>>>();
    wiener_coef_kernel<<<(NBATCH*NCHUNK*NBINS + 255) / 256, 256>>>(W);
    {
        size_t total = (size_t)NBATCH * NFRM * NBINS;
        wiener_apply_kernel<<<(unsigned)((total + 255) / 256), 256>>>();
    }
    istft_ola_kernel<<<NBATCH * NSRC * NSTRIP, 512>>>(out);
    {
        int total = NBATCH*NSRC * (NSTRIP - 1) * 3 * HOP;
        boundary_kernel<<<(total + 255) / 256, 256>>>(out);
    }
}

// round 17
// speedup vs baseline: 1.2316x; 1.0176x over previous
#include <cuda_runtime.h>
#include <math.h>

// ---------------- problem constants ----------------
#define NBATCH 2
#define NCH    2
#define NSRC   4
#define NFFT   4096
#define HOP    1024
#define NBINS  2049
#define NFRM   600
#define WINLEN 300
#define NCHUNK 2
#define TLEN   613376
#define PAD    2048
#define EPSV   1e-10f
#define SQEPS  1e-5f
#define OUTLEN (NFFT + HOP*(NFRM-1))   // 617472
#define NHOP   601
#define FOWN   17
#define NSTRIP 36

// exchange row strides (bank-conflict-free for float2/LDS.64, 512 cols)
#define ST1 514
#define ST2 520
#define SBUF (8*ST2)

// ---------------- device scratch ----------------
__device__ float2 d_rt[NBINS];
__device__ float  d_win[NFFT];
__device__ float  d_wsuminv[OUTLEN];
__device__ unsigned int d_maxsq[NBATCH*NCHUNK];
__device__ float4 d_X4[(size_t)NBATCH*NFRM*NBINS];             // (x0.re,x0.im,x1.re,x1.im)
__device__ float4 d_W[(size_t)NBATCH*NFRM*NBINS];              // ma*p*(w0,w1)
__device__ float  d_G[(size_t)NBATCH*NCHUNK*NBINS*4];          // raw G accumulators
__device__ float4 d_Gs[(size_t)NBATCH*NCHUNK*NBINS];           // scaled G
__device__ float  d_A[(size_t)NBATCH*NCHUNK*NBINS];            // sum of coefs
__device__ float  d_coef[(size_t)NBATCH*NCHUNK*NSRC*NBINS];    // per-source bin coef
// boundary handoff buffers: [ns][strip][3 hops][1024 samples], (ch0,ch1)
__device__ float2 d_head[(size_t)NBATCH*NSRC*NSTRIP*3*HOP];
__device__ float2 d_tail[(size_t)NBATCH*NSRC*NSTRIP*3*HOP];

__device__ __forceinline__ float2 cmul(float2 a, float2 b) {
    return make_float2(a.x*b.x - a.y*b.y, a.x*b.y + a.y*b.x);
}
__device__ __forceinline__ float2 cadd(float2 a, float2 b) { return make_float2(a.x+b.x, a.y+b.y); }
__device__ __forceinline__ float2 csub(float2 a, float2 b) { return make_float2(a.x-b.x, a.y-b.y); }

template<bool INV>
__device__ __forceinline__ float2 mul_pm_i(float2 d) {
    return INV ? make_float2(-d.y, d.x) : make_float2(d.y, -d.x);
}

// ---------------- init ----------------
__global__ void init_kernel() {
    int i = blockIdx.x * blockDim.x + threadIdx.x;
    if (i < NBINS) {
        double ang = -2.0 * M_PI * (double)i / (double)NFFT;
        d_rt[i] = make_float2((float)cos(ang), (float)sin(ang));
    }
    if (i < NFFT) {
        double w = 0.5 * (1.0 - cos(2.0 * M_PI * (double)i / (double)NFFT));
        d_win[i]  = (float)w;
    }
    if (i < NBATCH*NCHUNK) d_maxsq[i] = 0u;
}

// ---------------- init2: wsuminv (all-float) + zero G ----------------
__global__ void init2_kernel() {
    int i = blockIdx.x * blockDim.x + threadIdx.x;
    if (i < NBATCH*NCHUNK*NBINS*4) d_G[i] = 0.f;
    if (i >= OUTLEN) return;
    int fhi = min(NFRM - 1, i >> 10);
    int flo = max(0, (i - (NFFT - HOP)) >> 10);
    float wsum = 0.f;
    for (int f = flo; f <= fhi; f++) {
        float w = d_win[i - (f << 10)];
        wsum += w * w;
    }
    d_wsuminv[i] = 1.f / (wsum > 1e-11f ? wsum : 1.f);
}

// ---------------- radix-8 DFT in registers ----------------
template<bool INV>
__device__ __forceinline__ void dft8(const float2 a[8], float2 r[8]) {
    const float s = 0.70710678118654752440f;
    float2 t0 = cadd(a[0], a[4]);
    float2 t1 = csub(a[0], a[4]);
    float2 t2 = cadd(a[2], a[6]);
    float2 t3 = mul_pm_i<INV>(csub(a[2], a[6]));
    float2 E0 = cadd(t0, t2), E1 = cadd(t1, t3), E2 = csub(t0, t2), E3 = csub(t1, t3);
    float2 u0 = cadd(a[1], a[5]);
    float2 u1 = csub(a[1], a[5]);
    float2 u2 = cadd(a[3], a[7]);
    float2 u3 = mul_pm_i<INV>(csub(a[3], a[7]));
    float2 O0 = cadd(u0, u2), O1 = cadd(u1, u3), O2 = csub(u0, u2), O3 = csub(u1, u3);
    float2 O1t, O2t, O3t;
    if (!INV) {
        O1t = make_float2(s*(O1.x + O1.y), s*(O1.y - O1.x));
        O2t = make_float2(O2.y, -O2.x);
        O3t = make_float2(s*(O3.y - O3.x), -s*(O3.x + O3.y));
    } else {
        O1t = make_float2(s*(O1.x - O1.y), s*(O1.x + O1.y));
        O2t = make_float2(-O2.y, O2.x);
        O3t = make_float2(-s*(O3.x + O3.y), s*(O3.x - O3.y));
    }
    r[0] = cadd(E0, O0);  r[4] = csub(E0, O0);
    r[1] = cadd(E1, O1t); r[5] = csub(E1, O1t);
    r[2] = cadd(E2, O2t); r[6] = csub(E2, O2t);
    r[3] = cadd(E3, O3t); r[7] = csub(E3, O3t);
}

// product-tree twiddles
template<bool INV>
__device__ __forceinline__ void twiddle8(float2 r[8], int jm) {
    float2 w1 = d_rt[jm];
    if (INV) w1.y = -w1.y;
    float2 w2 = cmul(w1, w1);
    float2 w3 = cmul(w2, w1);
    float2 w4 = cmul(w2, w2);
    float2 w5 = cmul(w4, w1);
    float2 w6 = cmul(w4, w2);
    float2 w7 = cmul(w4, w3);
    r[1] = cmul(r[1], w1);
    r[2] = cmul(r[2], w2);
    r[3] = cmul(r[3], w3);
    r[4] = cmul(r[4], w4);
    r[5] = cmul(r[5], w5);
    r[6] = cmul(r[6], w6);
    r[7] = cmul(r[7], w7);
}

// ---------------- 4096-pt radix-8 Stockham, single buffer (6 syncs) ----------------
template<bool INV>
__device__ void fft4096_reg(float2 a[8], float2* __restrict__ sC, int tid) {
    float2 r[8];
    dft8<INV>(a, r);
    twiddle8<INV>(r, tid);
    #pragma unroll
    for (int q = 0; q < 8; q++) sC[q*ST1 + tid] = r[q];
    __syncthreads();
    #pragma unroll
    for (int q = 0; q < 8; q++) {
        int p = tid + q*512;
        a[q] = sC[(p & 7)*ST1 + (p >> 3)];
    }
    __syncthreads();
    dft8<INV>(a, r);
    twiddle8<INV>(r, tid - (tid & 7));
    #pragma unroll
    for (int q = 0; q < 8; q++) sC[q*ST2 + tid] = r[q];
    __syncthreads();
    #pragma unroll
    for (int q = 0; q < 8; q++) {
        int p = tid + q*512;
        int row = (p >> 3) & 7, col = ((p >> 6) << 3) | (p & 7);
        a[q] = sC[row*ST2 + col];
    }
    __syncthreads();
    dft8<INV>(a, r);
    twiddle8<INV>(r, tid - (tid & 63));
    #pragma unroll
    for (int q = 0; q < 8; q++) sC[q*ST2 + tid] = r[q];
    __syncthreads();
    #pragma unroll
    for (int q = 0; q < 8; q++) {
        int p = tid + q*512;
        int row = (p >> 6) & 7, col = ((p >> 9) << 6) | (p & 63);
        a[q] = sC[row*ST2 + col];
    }
    __syncthreads();
    dft8<INV>(a, r);
    #pragma unroll
    for (int q = 0; q < 8; q++) a[q] = r[q];
}

// ---------------- STFT: one block per (n,frame); both channels packed ----------------
__global__ __launch_bounds__(512) void stft_kernel(const float* __restrict__ audio) {
    __shared__ float2 sC[SBUF];
    __shared__ float redw[16];
    int bid = blockIdx.x;                 // n*600 + f
    int f   = bid % NFRM;
    int n   = bid / NFRM;
    int tid = threadIdx.x;
    const float* a0 = audio + (size_t)(n*NCH + 0) * TLEN;
    const float* a1 = audio + (size_t)(n*NCH + 1) * TLEN;
    int base = f * HOP - PAD;

    float2 a[8];
    #pragma unroll
    for (int q = 0; q < 8; q++) {
        int t = tid + q*512;
        int j = base + t;
        if (j < 0) j = -j; else if (j >= TLEN) j = 2*TLEN - 2 - j;
        float w = d_win[t];
        a[q] = make_float2(a0[j] * w, a1[j] * w);
    }
    fft4096_reg<false>(a, sC, tid);

    #pragma unroll
    for (int q = 0; q < 8; q++) sC[tid + q*512] = a[q];
    __syncthreads();

    float4* out = d_X4 + ((size_t)n * NFRM + f) * NBINS;
    float lmax = 0.f;
    for (int k = tid; k < NBINS; k += 512) {
        int kb = (NFFT - k) & (NFFT - 1);
        float2 Zk = sC[k];
        float2 Zm = sC[kb];
        float x0r = 0.5f*(Zk.x + Zm.x), x0i = 0.5f*(Zk.y - Zm.y);
        float x1r = 0.5f*(Zk.y + Zm.y), x1i = 0.5f*(Zm.x - Zk.x);
        out[k] = make_float4(x0r, x0i, x1r, x1i);
        lmax = fmaxf(lmax, fmaxf(x0r*x0r + x0i*x0i, x1r*x1r + x1i*x1i));
    }
    // warp-shuffle reduction, 1 block barrier
    #pragma unroll
    for (int o = 16; o > 0; o >>= 1)
        lmax = fmaxf(lmax, __shfl_xor_sync(0xffffffffu, lmax, o));
    if ((tid & 31) == 0) redw[tid >> 5] = lmax;
    __syncthreads();
    if (tid < 32) {
        float v = (tid < 16) ? redw[tid] : 0.f;
        #pragma unroll
        for (int o = 8; o > 0; o >>= 1)
            v = fmaxf(v, __shfl_xor_sync(0xffffffffu, v, o));
        if (tid == 0)
            atomicMax(&d_maxsq[n * NCHUNK + f / WINLEN], __float_as_uint(v));
    }
}

// ---------------- wiener pass A: raw spatial covariance G (t-split, atomic) ----------------
__global__ __launch_bounds__(256) void wiener_g_kernel() {
    __shared__ float sred[4][8][32];
    int nchunk = blockIdx.y;
    int seg = blockIdx.z;
    int n = nchunk >> 1, chunk = nchunk & 1;
    int tid = threadIdx.x;
    int bi = tid & 31, tg = tid >> 5;
    int b = blockIdx.x * 32 + bi;
    bool valid = (b < NBINS);
    int bc = valid ? b : 0;

    const float4* xp = d_X4 + ((size_t)n * NFRM + chunk*WINLEN + seg*15) * NBINS + bc;

    float g00 = 0.f, g11 = 0.f, g01r = 0.f, g01i = 0.f;
    for (int t = tg; t < 15; t += 8) {
        float4 v = xp[(size_t)t * NBINS];
        g00 += v.x*v.x + v.y*v.y;
        g11 += v.z*v.z + v.w*v.w;
        g01r += v.x*v.z + v.y*v.w;
        g01i += v.y*v.z - v.x*v.w;
    }
    sred[0][tg][bi] = g00; sred[1][tg][bi] = g11;
    sred[2][tg][bi] = g01r; sred[3][tg][bi] = g01i;
    __syncthreads();
    if (tg == 0 && valid) {
        g00 = g11 = g01r = g01i = 0.f;
        #pragma unroll
        for (int k = 0; k < 8; k++) {
            g00 += sred[0][k][bi]; g11 += sred[1][k][bi];
            g01r += sred[2][k][bi]; g01i += sred[3][k][bi];
        }
        float* gp = d_G + ((size_t)nchunk * NBINS + b) * 4;
        atomicAdd(gp + 0, g00);
        atomicAdd(gp + 1, g11);
        atomicAdd(gp + 2, g01r);
        atomicAdd(gp + 3, g01i);
    }
}

// ---------------- wiener pass B: per-bin coefs ----------------
__global__ void wiener_coef_kernel(const float* __restrict__ W) {
    int id = blockIdx.x * blockDim.x + threadIdx.x;
    if (id >= NBATCH*NCHUNK*NBINS) return;
    int b = id % NBINS;
    int nchunk = id / NBINS;
    float maxsq = __uint_as_float(d_maxsq[nchunk]);
    float ma = fmaxf(1.f, sqrtf(maxsq) * 0.1f);
    float inv_ma2 = 1.f / (ma * ma);
    const float* gp = d_G + (size_t)id * 4;
    float g00 = gp[0] * inv_ma2;
    float g11 = gp[1] * inv_ma2;
    float g01r = gp[2] * inv_ma2;
    float g01i = gp[3] * inv_ma2;
    float P = 0.5f * (g00 + g11);
    float A = 0.f;
    #pragma unroll
    for (int s = 0; s < NSRC; s++) {
        float m  = 1.f / (1.f + expf(-W[s * NBINS + b]));
        float m2 = m * m;
        float c = (m2 * m2) / (EPSV + m2 * P);
        A += c;
        d_coef[((size_t)(nchunk * NSRC + s)) * NBINS + b] = c;
    }
    d_Gs[id] = make_float4(g00, g11, g01r, g01i);
    d_A[id] = A;
}

// ---------------- wiener pass C: apply per (n,t,b) ----------------
__global__ __launch_bounds__(256) void wiener_apply_kernel() {
    size_t id = (size_t)blockIdx.x * blockDim.x + threadIdx.x;
    const size_t total = (size_t)NBATCH * NFRM * NBINS;
    if (id >= total) return;
    int b = (int)(id % NBINS);
    int nf = (int)(id / NBINS);
    int f = nf % NFRM;
    int n = nf / NFRM;
    int nchunk = n * NCHUNK + (f >= WINLEN ? 1 : 0);

    float maxsq = __uint_as_float(d_maxsq[nchunk]);
    float ma = fmaxf(1.f, sqrtf(maxsq) * 0.1f);
    float inv_ma = 1.f / ma;

    float4 v = __ldcs(&d_X4[id]);   // last reader: don't cache
    float4 g4 = d_Gs[(size_t)nchunk * NBINS + b];
    float A = d_A[(size_t)nchunk * NBINS + b];
    float g00 = g4.x, g11 = g4.y, g01r = g4.z, g01i = g4.w;

    float2 x0 = make_float2(v.x*inv_ma, v.y*inv_ma);
    float2 x1 = make_float2(v.z*inv_ma, v.w*inv_ma);
    float p = 0.5f * (x0.x*x0.x + x0.y*x0.y + x1.x*x1.x + x1.y*x1.y);
    float bt = p * A;
    float c00 = SQEPS + bt * g00;
    float c11 = SQEPS + bt * g11;
    float c01r = bt * g01r, c01i = bt * g01i;
    float det = c00 * c11 - (c01r*c01r + c01i*c01i);
    float idet = 1.f / det;
    float2 u0, u1;
    u0.x = idet * (c11 * x0.x - (c01r * x1.x - c01i * x1.y));
    u0.y = idet * (c11 * x0.y - (c01r * x1.y + c01i * x1.x));
    u1.x = idet * ((-c01r * x0.x - c01i * x0.y) + c00 * x1.x);
    u1.y = idet * (( c01i * x0.x - c01r * x0.y) + c00 * x1.y);
    float2 w0, w1;
    w0.x = g00 * u0.x + g01r * u1.x - g01i * u1.y;
    w0.y = g00 * u0.y + g01r * u1.y + g01i * u1.x;
    w1.x = g01r * u0.x + g01i * u0.y + g11 * u1.x;
    w1.y = g01r * u0.y - g01i * u0.x + g11 * u1.y;
    float sc = ma * p;
    d_W[id] = make_float4(sc*w0.x, sc*w0.y, sc*w1.x, sc*w1.y);
}

// ---------------- fused iSTFT + OLA, no halo (boundary handoff) ----------------
__global__ __launch_bounds__(512, 2) void istft_ola_kernel(float* __restrict__ out) {
    __shared__ float2 sC[SBUF];
    __shared__ float2 sAcc[NFFT];
    int bid = blockIdx.x;          // ns*NSTRIP + strip
    int strip = bid % NSTRIP;
    int ns = bid / NSTRIP;         // n*4 + s
    int n = ns >> 2;
    int s = ns & 3;
    int tid = threadIdx.x;

    int h0 = strip * FOWN;
    int fend = min(NFRM, h0 + FOWN);

    float* o0 = out + ((size_t)ns * NCH + 0) * TLEN;
    float* o1 = out + ((size_t)ns * NCH + 1) * TLEN;
    float2* headp = d_head + ((size_t)(ns * NSTRIP + strip) * 3) * HOP;
    float2* tailp = d_tail + ((size_t)(ns * NSTRIP + strip) * 3) * HOP;

    #pragma unroll
    for (int q = 0; q < 8; q++) sAcc[tid + q*512] = make_float2(0.f, 0.f);
    __syncthreads();

    const float inv_n = 1.f / (float)NFFT;

    for (int f = h0; f < fend; f++) {
        int chunk = f / WINLEN;
        const float4* Wrow = d_W + ((size_t)n * NFRM + f) * NBINS;
        const float*  crow = d_coef + ((size_t)((n*NCHUNK + chunk) * NSRC + s)) * NBINS;

        float2 a[8];
        #pragma unroll
        for (int q = 0; q < 8; q++) {
            int j = tid + q*512;
            int k = (j <= 2048) ? j : (NFFT - j);
            float4 w4 = Wrow[k];
            float cc  = crow[k];
            if (j <= 2048)
                a[q] = make_float2(cc * (w4.x - w4.w), cc * (w4.y + w4.z));
            else
                a[q] = make_float2(cc * (w4.x + w4.w), cc * (w4.z - w4.y));
        }
        fft4096_reg<true>(a, sC, tid);

        int fb = (f << 10);
        bool head = (f - h0 < 3) && (h0 > 0);   // partial hop (prev strip contributes)
        // finalize hop f: ring + in-register a[0],a[1]; zero slots
        #pragma unroll
        for (int u = 0; u < 2; u++) {
            int p = tid + u*512;
            int jj = fb + p;
            int slot = jj & (NFFT - 1);
            float w = inv_n * d_win[p];
            float2 v = sAcc[slot];
            v.x += a[u].x * w;
            v.y += a[u].y * w;
            sAcc[slot] = make_float2(0.f, 0.f);
            if (head) {
                __stcs(&headp[(f - h0) * HOP + p], v);
            } else {
                int t = jj - PAD;
                if (t >= 0 && t < TLEN) {
                    float wi = d_wsuminv[jj];
                    __stcs(&o0[t], v.x * wi);
                    __stcs(&o1[t], v.y * wi);
                }
            }
        }
        // tail accumulate (hops f+1..f+3): disjoint slots from finalize
        #pragma unroll
        for (int q = 2; q < 8; q++) {
            int p = tid + q*512;
            int slot = (fb + p) & (NFFT - 1);
            float w = inv_n * d_win[p];
            float2 acc = sAcc[slot];
            sAcc[slot] = make_float2(acc.x + a[q].x * w, acc.y + a[q].y * w);
        }
        __syncthreads();
    }

    if (fend < NFRM) {
        // hand off ring tail (partials for hops fend..fend+2) to next strip
        #pragma unroll
        for (int j = 0; j < 3; j++) {
            int hb = (fend + j) << 10;
            #pragma unroll
            for (int u = 0; u < 2; u++) {
                int p = tid + u*512;
                __stcs(&tailp[j * HOP + p], sAcc[(hb + p) & (NFFT - 1)]);
            }
        }
    } else {
        // final strip: hop 600 complete from ring (frames 597..599 in-strip)
        int j0 = (NFRM << 10);   // 614400
        #pragma unroll
        for (int u = 0; u < 2; u++) {
            int jj = j0 + tid + u*512;
            float2 v = sAcc[jj & (NFFT - 1)];
            int t = jj - PAD;
            float wi = d_wsuminv[jj];
            __stcs(&o0[t], v.x * wi);
            __stcs(&o1[t], v.y * wi);
        }
    }
}

// ---------------- boundary cleanup: out = (head[s] + tail[s-1]) * wsuminv ----------------
__global__ __launch_bounds__(256) void boundary_kernel(float* __restrict__ out) {
    int id = blockIdx.x * blockDim.x + threadIdx.x;
    const int total = NBATCH*NSRC * (NSTRIP - 1) * 3 * HOP;
    if (id >= total) return;
    int p  = id & (HOP - 1);
    int j  = (id >> 10) % 3;
    int sp = ((id >> 10) / 3) % (NSTRIP - 1);
    int ns = (id >> 10) / (3 * (NSTRIP - 1));
    int strip = sp + 1;                          // strips 1..NSTRIP-1
    int hop = strip * FOWN + j;
    float2 h = __ldcs(&d_head[((size_t)(ns * NSTRIP + strip) * 3 + j) * HOP + p]);
    float2 t2 = __ldcs(&d_tail[((size_t)(ns * NSTRIP + strip - 1) * 3 + j) * HOP + p]);
    int jj = (hop << 10) + p;
    int t = jj - PAD;
    if (t < 0 || t >= TLEN) return;
    float wi = d_wsuminv[jj];
    __stcs(&out[((size_t)ns * NCH + 0) * TLEN + t], (h.x + t2.x) * wi);
    __stcs(&out[((size_t)ns * NCH + 1) * TLEN + t], (h.y + t2.y) * wi);
}

// ---------------- launch ----------------
extern "C" void kernel_launch(void* const* d_in, const int* in_sizes, int n_in,
                              void* d_out, int out_size) {
    const float* audio = (const float*)d_in[0];
    const float* W     = (const float*)d_in[1];
    float* out = (float*)d_out;

    init_kernel<<<16, 256>>>();
    init2_kernel<<<(OUTLEN + 255) / 256, 256>>>();
    stft_kernel<<<NBATCH * NFRM, 512>>>(audio);
    wiener_g_kernel<<<dim3((NBINS + 31) / 32, NBATCH * NCHUNK, 20), 256>>>();
    wiener_coef_kernel<<<(NBATCH*NCHUNK*NBINS + 255) / 256, 256>>>(W);
    {
        size_t total = (size_t)NBATCH * NFRM * NBINS;
        wiener_apply_kernel<<<(unsigned)((total + 255) / 256), 256>>>();
    }
    istft_ola_kernel<<<NBATCH * NSRC * NSTRIP, 512>>>(out);
    {
        int total = NBATCH*NSRC * (NSTRIP - 1) * 3 * HOP;
        boundary_kernel<<<(total + 255) / 256, 256>>>(out);
    }
}